// round 3
// baseline (speedup 1.0000x reference)
#include <cuda_runtime.h>

#define NR 512
#define NZ 512

// Quad table: qt[ir*512+iz] = (tt[ir][iz], tt[ir][iz+1], tt[ir+1][iz], tt[ir+1][iz+1])
__device__ float4 g_qt[NR * NZ];

__global__ void __launch_bounds__(256) build_qt_kernel(const float* __restrict__ tt) {
    int t = blockIdx.x * blockDim.x + threadIdx.x;
    if (t >= NR * NZ) return;
    int ir = t >> 9;
    int iz = t & 511;
    if (ir >= NR - 1 || iz >= NZ - 1) return;
    float4 q;
    q.x = tt[t];            // Q11
    q.y = tt[t + 1];        // Q12
    q.z = tt[t + NZ];       // Q21
    q.w = tt[t + NZ + 1];   // Q22
    g_qt[t] = q;
}

// 8 points per thread: phase 1 computes indices+fracs, phase 2 issues all 8
// gathers (front-batched LDGs -> 8 outstanding per thread), phase 3 FMAs.
__global__ void __launch_bounds__(256) interp_kernel(
    const float* __restrict__ r,
    const float* __restrict__ z,
    float* __restrict__ out,
    int n8)
{
    int i = blockIdx.x * blockDim.x + threadIdx.x;
    if (i >= n8) return;

    const float4* r4 = reinterpret_cast<const float4*>(r);
    const float4* z4 = reinterpret_cast<const float4*>(z);

    float4 rv[2], zv[2];
    rv[0] = r4[2 * i];  rv[1] = r4[2 * i + 1];
    zv[0] = z4[2 * i];  zv[1] = z4[2 * i + 1];

    float rr[8] = {rv[0].x, rv[0].y, rv[0].z, rv[0].w,
                   rv[1].x, rv[1].y, rv[1].z, rv[1].w};
    float zz[8] = {zv[0].x, zv[0].y, zv[0].z, zv[0].w,
                   zv[1].x, zv[1].y, zv[1].z, zv[1].w};

    float fr[8], fz[8];
    int   idx[8];

#pragma unroll
    for (int k = 0; k < 8; k++) {
        float frf = fminf(fmaxf(floorf(rr[k]), 0.0f), (float)(NR - 2));
        float fzf = fminf(fmaxf(floorf(zz[k]), 0.0f), (float)(NZ - 2));
        fr[k] = rr[k] - frf;   // wr1; wr0 = 1 - fr
        fz[k] = zz[k] - fzf;   // wz1; wz0 = 1 - fz
        idx[k] = ((int)frf << 9) + (int)fzf;
    }

    float4 q[8];
#pragma unroll
    for (int k = 0; k < 8; k++) {
        q[k] = __ldg(&g_qt[idx[k]]);
    }

    float res[8];
#pragma unroll
    for (int k = 0; k < 8; k++) {
        float wr1 = fr[k], wr0 = 1.0f - fr[k];
        float wz1 = fz[k], wz0 = 1.0f - fz[k];
        res[k] = q[k].x * (wr0 * wz0)
               + q[k].z * (wr1 * wz0)
               + q[k].y * (wr0 * wz1)
               + q[k].w * (wr1 * wz1);
    }

    float4* o4 = reinterpret_cast<float4*>(out);
    float4 o0, o1;
    o0.x = res[0]; o0.y = res[1]; o0.z = res[2]; o0.w = res[3];
    o1.x = res[4]; o1.y = res[5]; o1.z = res[6]; o1.w = res[7];
    o4[2 * i]     = o0;
    o4[2 * i + 1] = o1;
}

extern "C" void kernel_launch(void* const* d_in, const int* in_sizes, int n_in,
                              void* d_out, int out_size) {
    const float* r  = (const float*)d_in[0];
    const float* z  = (const float*)d_in[1];
    const float* tt = (const float*)d_in[2];
    float* out = (float*)d_out;

    int n = in_sizes[0];          // 20,000,000
    int n8 = n / 8;               // 2,500,000

    build_qt_kernel<<<(NR * NZ + 255) / 256, 256>>>(tt);

    int threads = 256;
    int blocks = (n8 + threads - 1) / threads;
    interp_kernel<<<blocks, threads>>>(r, z, out, n8);
}

// round 4
// speedup vs baseline: 1.0329x; 1.0329x over previous
#include <cuda_runtime.h>

#define NR 512
#define NZ 512

// Quad table: qt[ir*512+iz] = (tt[ir][iz], tt[ir][iz+1], tt[ir+1][iz], tt[ir+1][iz+1])
__device__ float4 g_qt[NR * NZ];

__global__ void __launch_bounds__(256) build_qt_kernel(const float* __restrict__ tt) {
    int t = blockIdx.x * blockDim.x + threadIdx.x;
    if (t >= NR * NZ) return;
    int ir = t >> 9;
    int iz = t & 511;
    if (ir >= NR - 1 || iz >= NZ - 1) return;
    float4 q;
    q.x = tt[t];            // Q11
    q.y = tt[t + 1];        // Q12
    q.z = tt[t + NZ];       // Q21
    q.w = tt[t + NZ + 1];   // Q22
    g_qt[t] = q;
}

// 8 points/thread, 64-reg budget (launch_bounds minBlocks=4) so all 8 float4
// gathers stay live simultaneously -> 256 outstanding gathers per SM at occ=32w.
__global__ void __launch_bounds__(256, 4) interp_kernel(
    const float* __restrict__ r,
    const float* __restrict__ z,
    float* __restrict__ out,
    int n8)
{
    int i = blockIdx.x * blockDim.x + threadIdx.x;
    if (i >= n8) return;

    const float4* r4 = reinterpret_cast<const float4*>(r);
    const float4* z4 = reinterpret_cast<const float4*>(z);

    float4 rv[2], zv[2];
    rv[0] = r4[2 * i];  rv[1] = r4[2 * i + 1];
    zv[0] = z4[2 * i];  zv[1] = z4[2 * i + 1];

    float rr[8] = {rv[0].x, rv[0].y, rv[0].z, rv[0].w,
                   rv[1].x, rv[1].y, rv[1].z, rv[1].w};
    float zz[8] = {zv[0].x, zv[0].y, zv[0].z, zv[0].w,
                   zv[1].x, zv[1].y, zv[1].z, zv[1].w};

    float fr[8], fz[8];
    int   idx[8];

#pragma unroll
    for (int k = 0; k < 8; k++) {
        float frf = fminf(fmaxf(floorf(rr[k]), 0.0f), (float)(NR - 2));
        float fzf = fminf(fmaxf(floorf(zz[k]), 0.0f), (float)(NZ - 2));
        fr[k] = rr[k] - frf;   // wr1; wr0 = 1 - fr
        fz[k] = zz[k] - fzf;   // wz1; wz0 = 1 - fz
        idx[k] = ((int)frf << 9) + (int)fzf;
    }

    // Front-batched gathers: all 8 LDG.128 issued before any consumer.
    float4 q[8];
#pragma unroll
    for (int k = 0; k < 8; k++) {
        q[k] = __ldg(&g_qt[idx[k]]);
    }

    float res[8];
#pragma unroll
    for (int k = 0; k < 8; k++) {
        float wr1 = fr[k], wr0 = 1.0f - fr[k];
        float wz1 = fz[k], wz0 = 1.0f - fz[k];
        res[k] = q[k].x * (wr0 * wz0)
               + q[k].z * (wr1 * wz0)
               + q[k].y * (wr0 * wz1)
               + q[k].w * (wr1 * wz1);
    }

    float4* o4 = reinterpret_cast<float4*>(out);
    float4 o0, o1;
    o0.x = res[0]; o0.y = res[1]; o0.z = res[2]; o0.w = res[3];
    o1.x = res[4]; o1.y = res[5]; o1.z = res[6]; o1.w = res[7];
    o4[2 * i]     = o0;
    o4[2 * i + 1] = o1;
}

extern "C" void kernel_launch(void* const* d_in, const int* in_sizes, int n_in,
                              void* d_out, int out_size) {
    const float* r  = (const float*)d_in[0];
    const float* z  = (const float*)d_in[1];
    const float* tt = (const float*)d_in[2];
    float* out = (float*)d_out;

    int n = in_sizes[0];          // 20,000,000
    int n8 = n / 8;               // 2,500,000

    build_qt_kernel<<<(NR * NZ + 255) / 256, 256>>>(tt);

    int threads = 256;
    int blocks = (n8 + threads - 1) / threads;
    interp_kernel<<<blocks, threads>>>(r, z, out, n8);
}

// round 5
// speedup vs baseline: 1.1399x; 1.1036x over previous
#include <cuda_runtime.h>

#define NR 512
#define NZ 512

// Quad table: qt[ir*512+iz] = (tt[ir][iz], tt[ir][iz+1], tt[ir+1][iz], tt[ir+1][iz+1])
__device__ float4 g_qt[NR * NZ];

// Vectorized build: each thread covers 4 consecutive iz of one row.
// Loads: 1 float4 + 1 scalar per row (x2 rows), writes 4x float4.
__global__ void __launch_bounds__(256) build_qt_kernel(const float* __restrict__ tt) {
    int t = blockIdx.x * blockDim.x + threadIdx.x;   // 65536 threads
    int ir = t >> 7;            // 512 rows
    int iz4 = (t & 127) << 2;   // 0,4,...,508
    if (ir >= NR - 1) return;

    const float* row0 = tt + ir * NZ + iz4;
    const float* row1 = row0 + NZ;

    float4 a = *reinterpret_cast<const float4*>(row0);
    float4 c = *reinterpret_cast<const float4*>(row1);
    // next element after the float4 (guard the last column block)
    bool last = (iz4 + 4 >= NZ);
    float b = last ? 0.0f : row0[4];
    float d = last ? 0.0f : row1[4];

    float a4[5] = {a.x, a.y, a.z, a.w, b};
    float c4[5] = {c.x, c.y, c.z, c.w, d};

    float4* q = &g_qt[ir * NZ + iz4];
#pragma unroll
    for (int k = 0; k < 4; k++) {
        if (iz4 + k >= NZ - 1) break;
        float4 v;
        v.x = a4[k];     // Q11
        v.y = a4[k + 1]; // Q12
        v.z = c4[k];     // Q21
        v.w = c4[k + 1]; // Q22
        q[k] = v;
    }
}

// 4 points/thread (R2 config: regs=32, ~full occupancy = proven fastest).
// Streaming hints keep the quad table resident in L1.
__global__ void __launch_bounds__(256) interp_kernel(
    const float* __restrict__ r,
    const float* __restrict__ z,
    float* __restrict__ out,
    int n4)
{
    int i = blockIdx.x * blockDim.x + threadIdx.x;
    if (i >= n4) return;

    float4 rv = __ldcs(reinterpret_cast<const float4*>(r) + i);
    float4 zv = __ldcs(reinterpret_cast<const float4*>(z) + i);

    float rr[4] = {rv.x, rv.y, rv.z, rv.w};
    float zz[4] = {zv.x, zv.y, zv.z, zv.w};
    float res[4];

#pragma unroll
    for (int k = 0; k < 4; k++) {
        float frf = fminf(fmaxf(floorf(rr[k]), 0.0f), (float)(NR - 2));
        float fzf = fminf(fmaxf(floorf(zz[k]), 0.0f), (float)(NZ - 2));
        int ir0 = (int)frf;
        int iz0 = (int)fzf;

        float wr1 = rr[k] - frf;
        float wr0 = 1.0f - wr1;
        float wz1 = zz[k] - fzf;
        float wz0 = 1.0f - wz1;

        float4 q = __ldg(&g_qt[(ir0 << 9) + iz0]);

        res[k] = q.x * (wr0 * wz0)
               + q.z * (wr1 * wz0)
               + q.y * (wr0 * wz1)
               + q.w * (wr1 * wz1);
    }

    float4 o;
    o.x = res[0]; o.y = res[1]; o.z = res[2]; o.w = res[3];
    __stcs(reinterpret_cast<float4*>(out) + i, o);
}

extern "C" void kernel_launch(void* const* d_in, const int* in_sizes, int n_in,
                              void* d_out, int out_size) {
    const float* r  = (const float*)d_in[0];
    const float* z  = (const float*)d_in[1];
    const float* tt = (const float*)d_in[2];
    float* out = (float*)d_out;

    int n = in_sizes[0];          // 20,000,000
    int n4 = n / 4;               // 5,000,000

    build_qt_kernel<<<(NR * 128 + 255) / 256, 256>>>(tt);

    int threads = 256;
    int blocks = (n4 + threads - 1) / threads;
    interp_kernel<<<blocks, threads>>>(r, z, out, n4);
}

// round 6
// speedup vs baseline: 1.1544x; 1.0127x over previous
#include <cuda_runtime.h>

#define NR 512
#define NZ 512

// Quad table: qt[ir*512+iz] = (tt[ir][iz], tt[ir][iz+1], tt[ir+1][iz], tt[ir+1][iz+1])
__device__ float4 g_qt[NR * NZ];

// Vectorized build: each thread covers 4 consecutive iz of one row.
__global__ void __launch_bounds__(256) build_qt_kernel(const float* __restrict__ tt) {
    int t = blockIdx.x * blockDim.x + threadIdx.x;   // 65536 threads
    int ir = t >> 7;            // row
    int iz4 = (t & 127) << 2;   // 0,4,...,508
    if (ir >= NR - 1) return;

    const float* row0 = tt + ir * NZ + iz4;
    const float* row1 = row0 + NZ;

    float4 a = *reinterpret_cast<const float4*>(row0);
    float4 c = *reinterpret_cast<const float4*>(row1);
    bool last = (iz4 + 4 >= NZ);
    float b = last ? 0.0f : row0[4];
    float d = last ? 0.0f : row1[4];

    float a4[5] = {a.x, a.y, a.z, a.w, b};
    float c4[5] = {c.x, c.y, c.z, c.w, d};

    float4* q = &g_qt[ir * NZ + iz4];
#pragma unroll
    for (int k = 0; k < 4; k++) {
        if (iz4 + k >= NZ - 1) break;
        float4 v;
        v.x = a4[k];     // Q11
        v.y = a4[k + 1]; // Q12
        v.z = c4[k];     // Q21
        v.w = c4[k + 1]; // Q22
        q[k] = v;
    }
}

// 4 points/thread (proven fastest config: regs=32, ~full occupancy).
// PDL: prolog (streaming loads + index math) runs while build drains;
// cudaGridDependencySynchronize() guards the quad-table gathers.
__global__ void __launch_bounds__(256) interp_kernel(
    const float* __restrict__ r,
    const float* __restrict__ z,
    float* __restrict__ out,
    int n4)
{
    int i = blockIdx.x * blockDim.x + threadIdx.x;
    if (i >= n4) {
        cudaGridDependencySynchronize();
        return;
    }

    float4 rv = __ldcs(reinterpret_cast<const float4*>(r) + i);
    float4 zv = __ldcs(reinterpret_cast<const float4*>(z) + i);

    float rr[4] = {rv.x, rv.y, rv.z, rv.w};
    float zz[4] = {zv.x, zv.y, zv.z, zv.w};

    float fr[4], fz[4];
    int   idx[4];
#pragma unroll
    for (int k = 0; k < 4; k++) {
        float frf = fminf(fmaxf(floorf(rr[k]), 0.0f), (float)(NR - 2));
        float fzf = fminf(fmaxf(floorf(zz[k]), 0.0f), (float)(NZ - 2));
        fr[k] = rr[k] - frf;
        fz[k] = zz[k] - fzf;
        idx[k] = (((int)frf) << 9) + (int)fzf;
    }

    // Wait for build_qt_kernel to complete before gathering from g_qt.
    cudaGridDependencySynchronize();

    float res[4];
#pragma unroll
    for (int k = 0; k < 4; k++) {
        float4 q = __ldg(&g_qt[idx[k]]);
        float wr1 = fr[k], wr0 = 1.0f - fr[k];
        float wz1 = fz[k], wz0 = 1.0f - fz[k];
        res[k] = q.x * (wr0 * wz0)
               + q.z * (wr1 * wz0)
               + q.y * (wr0 * wz1)
               + q.w * (wr1 * wz1);
    }

    float4 o;
    o.x = res[0]; o.y = res[1]; o.z = res[2]; o.w = res[3];
    __stcs(reinterpret_cast<float4*>(out) + i, o);
}

extern "C" void kernel_launch(void* const* d_in, const int* in_sizes, int n_in,
                              void* d_out, int out_size) {
    const float* r  = (const float*)d_in[0];
    const float* z  = (const float*)d_in[1];
    const float* tt = (const float*)d_in[2];
    float* out = (float*)d_out;

    int n = in_sizes[0];          // 20,000,000
    int n4 = n / 4;               // 5,000,000

    build_qt_kernel<<<(NR * 128 + 255) / 256, 256>>>(tt);

    int threads = 256;
    int blocks = (n4 + threads - 1) / threads;

    // Launch interp with programmatic dependent launch: it may begin while
    // build is still draining; the device-side griddepsync provides ordering.
    cudaLaunchAttribute attrs[1];
    attrs[0].id = cudaLaunchAttributeProgrammaticStreamSerialization;
    attrs[0].val.programmaticStreamSerializationAllowed = 1;

    cudaLaunchConfig_t cfg = {};
    cfg.gridDim = dim3((unsigned)blocks);
    cfg.blockDim = dim3((unsigned)threads);
    cfg.dynamicSmemBytes = 0;
    cfg.stream = 0;
    cfg.attrs = attrs;
    cfg.numAttrs = 1;

    cudaLaunchKernelEx(&cfg, interp_kernel, r, z, out, n4);
}